// round 16
// baseline (speedup 1.0000x reference)
#include <cuda_runtime.h>
#include <math.h>
#include <stdint.h>

#define N_P   33600
#define NPAD  33792                 // 132 * 256
#define N_G   256
#define N_C   80
#define KK    13
#define NCHUNK 132
#define GSPLIT 2
#define GHALF  (N_G / GSPLIT)       // 128
#define CAPC  2048                  // cost-pool capacity per GT
#define CAPI  4096                  // iou-pool capacity per GT
#define COST_T 96.0f                // screening threshold: cost >= scp - 3e-7
#define DGATE 4.9872f               // scp < 97  <=>  dist < 4.9872
#define UMAX  0xFFFFFFFFFFFFFFFFull

typedef unsigned long long u64;
typedef unsigned int u32;

// ---------------- scratch (device globals; zero-initialized) ----------------
__device__ float4 g_pk0[NPAD];                // pred bbox x1,y1,x2,y2
__device__ float4 g_pk1[NPAD];                // px, py, 1/stride, +-area
__device__ int    g_cnt [N_P];                // starts 0; reset by resolve
__device__ int    g_mgt [N_P];
__device__ u64    g_amin[NPAD];               // INVERTED {costbits,j} keys; 0 = none
__device__ int    g_icnt[N_G];                // starts 0; reset by resolve
__device__ int    g_ccnt[N_G];
__device__ float  g_ipool[N_G * CAPI];        // iou>0 values
__device__ u64    g_cpool[N_G * CAPC];        // {costbits, prior idx} for cost<T

// ---------------- fast approx intrinsics ------------------------------------
__device__ __forceinline__ float ex2a(float x){ float r; asm("ex2.approx.f32 %0,%1;" : "=f"(r) : "f"(x)); return r; }
__device__ __forceinline__ float lg2a(float x){ float r; asm("lg2.approx.f32 %0,%1;" : "=f"(r) : "f"(x)); return r; }
__device__ __forceinline__ float sqrta(float x){ float r; asm("sqrt.approx.f32 %0,%1;" : "=f"(r) : "f"(x)); return r; }
__device__ __forceinline__ float rcpa(float x){ float r; asm("rcp.approx.f32 %0,%1;" : "=f"(r) : "f"(x)); return r; }

// ---------------- math helpers (identical everywhere) -----------------------
__device__ __forceinline__ float iou_fast(float4 A, float Pw, float4 b, float area_b) {
    float area_a = fabsf(Pw);
    float ltx = fmaxf(A.x, b.x), lty = fmaxf(A.y, b.y);
    float rbx = fminf(A.z, b.z), rby = fminf(A.w, b.w);
    float w = fmaxf(rbx - ltx, 0.0f), h = fmaxf(rby - lty, 0.0f);
    float inter = w * h;
    float uni = (area_a + area_b) - inter;
    return inter * rcpa(fmaxf(uni, 1e-6f));
}

__device__ __forceinline__ float iou_exact(float4 A, float Pw, float4 b, float area_b) {
    float area_a = fabsf(Pw);
    float ltx = fmaxf(A.x, b.x), lty = fmaxf(A.y, b.y);
    float rbx = fminf(A.z, b.z), rby = fminf(A.w, b.w);
    float w = fmaxf(rbx - ltx, 0.0f), h = fmaxf(rby - lty, 0.0f);
    float inter = w * h;
    float uni = (area_a + area_b) - inter;
    return __fdiv_rn(inter, fmaxf(uni, 1e-6f));
}

__device__ __forceinline__ float cost_tail(float iou, float d2, float inv_st, float l) {
    float dist = sqrta(d2) * inv_st;
    float scp = ex2a(__fmaf_rn(dist, 3.321928094887362f, -9.965784284662087f));
    float e   = ex2a(fabsf(l) * -1.4426950408889634f);
    float inv = rcpa(1.0f + e);
    float s   = (l >= 0.0f) ? inv : e * inv;
    float mm  = __fmaf_rn(lg2a(1.0f + e), 0.6931471805599453f, fmaxf(l, 0.0f));
    float d = iou - s;
    float scale = d * d;
    float bce = __fmaf_rn(-l, iou, mm);
    float ic = lg2a(iou + 1e-7f) * -2.0794415416798357f;
    return __fmaf_rn(bce, scale, ic + scp);
}

// ---------------- lane-local sorted-13 inserts -------------------------------
__device__ __forceinline__ void ins13_iou(float* a, float v) {
    if (v > a[KK-1]) {
        a[KK-1] = v;
        #pragma unroll
        for (int k = KK-1; k > 0; k--)
            if (a[k] > a[k-1]) { float t = a[k-1]; a[k-1] = a[k]; a[k] = t; }
    }
}
__device__ __forceinline__ void ins13_key(u64* a, u64 v) {
    if (v < a[KK-1]) {
        a[KK-1] = v;
        #pragma unroll
        for (int k = KK-1; k > 0; k--)
            if (a[k] < a[k-1]) { u64 t = a[k-1]; a[k-1] = a[k]; a[k] = t; }
    }
}

// interleaved 13-round warp extraction from per-lane sorted lists (length L).
template<int L>
__device__ __forceinline__ void warp_extract13(float* li, u64* lk,
                                               float& myv, u64& myk) {
    int lane = threadIdx.x & 31;
    myv = 0.0f; myk = UMAX;
    #pragma unroll
    for (int r = 0; r < KK; r++) {
        u32 hb = __float_as_uint(li[0]);
        u32 hc = (u32)(lk[0] >> 32);
        u32 hi = (u32)lk[0];
        u32 mb = __reduce_max_sync(0xFFFFFFFFu, hb);
        u32 mc = __reduce_min_sync(0xFFFFFFFFu, hc);
        u32 cand = (hc == mc) ? hi : 0xFFFFFFFFu;
        u32 mi = __reduce_min_sync(0xFFFFFFFFu, cand);
        if (lane == r) {
            myv = __uint_as_float(mb);
            myk = (((u64)mc) << 32) | mi;
        }
        u32 ballv = __ballot_sync(0xFFFFFFFFu, hb == mb);
        if (lane == (__ffs(ballv) - 1)) {
            #pragma unroll
            for (int k = 0; k < L-1; k++) li[k] = li[k+1];
            li[L-1] = 0.0f;
        }
        u32 ballk = __ballot_sync(0xFFFFFFFFu, (hc == mc) && (hi == mi));
        if (lane == (__ffs(ballk) - 1)) {
            #pragma unroll
            for (int k = 0; k < L-1; k++) lk[k] = lk[k+1];
            lk[L-1] = UMAX;
        }
    }
}

// ---------------- kernel S: pack + d2-gated pairwise scan --------------------
__global__ void __launch_bounds__(256) pair_scan_kernel(const float* __restrict__ ps,
                                                        const float* __restrict__ priors,
                                                        const float* __restrict__ pb,
                                                        const float* __restrict__ gtb,
                                                        const int*   __restrict__ glab) {
    __shared__ float4 svb[N_G];         // validity boxes (degenerate for pads)
    __shared__ float4 sgt[GHALF];       // raw GT boxes (my half)
    __shared__ float4 smt[GHALF];       // area, cx, cy
    __shared__ int    slab[GHALF];
    int tid = threadIdx.x;
    int chunk = blockIdx.x;             // 0..131
    int gbase = blockIdx.y * GHALF;     // 0 or 128

    {
        float4 B = ((const float4*)gtb)[tid];
        bool pad = ((B.x + B.y) + (B.z + B.w)) > 0.0f;
        svb[tid] = pad ? B : make_float4(1e30f, 1e30f, -1e30f, -1e30f);
    }
    if (tid < GHALF) {
        int j = gbase + tid;
        float4 B = ((const float4*)gtb)[j];
        sgt[tid] = B;
        smt[tid] = make_float4((B.z - B.x) * (B.w - B.y),
                               (B.x + B.z) * 0.5f, (B.y + B.w) * 0.5f, 0.0f);
        slab[tid] = glab[j];
    }
    __syncthreads();

    // ---- pack this chunk's prior in registers ----
    int i = chunk * 256 + tid;
    float4 A, P;
    if (i < N_P) {
        float4 PR = ((const float4*)priors)[i];
        A = ((const float4*)pb)[i];
        float px = PR.x, py = PR.y;
        bool any = false;
        for (int j = 0; j < N_G; j++) {
            float4 B = svb[j];
            if ((px > B.x) && (py > B.y) && (px < B.z) && (py < B.w)) { any = true; break; }
        }
        float area = (A.z - A.x) * (A.w - A.y);
        P = make_float4(px, py, rcpa(PR.z), any ? area : -area);
    } else {
        A = make_float4(0.0f, 0.0f, 0.0f, 0.0f);
        P = make_float4(0.0f, 0.0f, 1.0f, -1.0f);
    }
    if (blockIdx.y == 0) { g_pk0[i] = A; g_pk1[i] = P; }   // for select-fb / resolve

    bool valid = P.w > 0.0f;
    int lane = tid & 31;
    u32 lt_mask = (1u << lane) - 1u;
    const float* psrow = ps + (size_t)i * N_C;
    float stv = __fdiv_rn(DGATE, P.z);
    float d2max = valid ? stv * stv : -1.0f;

    u64 besti = 0;                      // inverted key; 0 = none
    #pragma unroll 4
    for (int jj = 0; jj < GHALF; jj++) {
        int j = gbase + jj;
        float4 b  = sgt[jj];
        float4 m4 = smt[jj];
        float iou = iou_fast(A, P.w, b, m4.x);

        // iou pool (iou > 0)
        bool pi = iou > 0.0f;
        u32 mi = __ballot_sync(0xFFFFFFFFu, pi);
        if (mi) {
            int leader = __ffs(mi) - 1;
            int base;
            if (lane == leader) base = atomicAdd(&g_icnt[j], __popc(mi));
            base = __shfl_sync(0xFFFFFFFFu, base, leader);
            if (pi) {
                int slot = base + __popc(mi & lt_mask);
                if (slot < CAPI) g_ipool[j * CAPI + slot] = iou;
            }
        }

        // cost: d2 gate, then full tail for the rare near pairs
        float dx = P.x - m4.y, dy = P.y - m4.z;
        float d2 = __fmaf_rn(dx, dx, dy * dy);
        bool pc = false;
        float cost = 1e8f;
        if (d2 < d2max) {
            float l = __ldg(psrow + slab[jj]);
            cost = cost_tail(iou, d2, P.z, l);
            pc = cost < COST_T;
            u64 ik = ~((((u64)__float_as_uint(cost)) << 32) | (u32)j);
            if (ik > besti) besti = ik;
        }
        u32 mc = __ballot_sync(0xFFFFFFFFu, pc);
        if (mc) {
            int leader = __ffs(mc) - 1;
            int base;
            if (lane == leader) base = atomicAdd(&g_ccnt[j], __popc(mc));
            base = __shfl_sync(0xFFFFFFFFu, base, leader);
            if (pc) {
                int slot = base + __popc(mc & lt_mask);
                if (slot < CAPC)
                    g_cpool[j * CAPC + slot] =
                        (((u64)__float_as_uint(cost)) << 32) | (u32)i;
            }
        }
    }
    // inverted-key argmin: exact for multi priors (min cost < 96 < gated-out costs)
    if (besti) atomicMax(&g_amin[i], besti);
}

// ---------------- kernel M: per-GT exact top-13 from pools + scatter ---------
__global__ void __launch_bounds__(256) select_kernel(const float* __restrict__ ps,
                                                     const float* __restrict__ gtb,
                                                     const int*   __restrict__ glab) {
    int j = blockIdx.x;
    int tid = threadIdx.x;
    int w = tid >> 5, lane = tid & 31;

    int cntI = g_icnt[j];
    int cntC = g_ccnt[j];
    bool fb = (cntC < KK) || (cntC > CAPC) || (cntI > CAPI);

    float li[KK]; u64 lk[KK];
    #pragma unroll
    for (int k = 0; k < KK; k++) { li[k] = 0.0f; lk[k] = UMAX; }

    if (!fb) {
        const float* ip = g_ipool + j * CAPI;
        const u64*   cp = g_cpool + j * CAPC;
        for (int t = tid; t < cntI; t += 256) ins13_iou(li, ip[t]);
        for (int t = tid; t < cntC; t += 256) ins13_key(lk, cp[t]);
    } else {
        // exact full-column rescan (correctness guarantee; ~never runs)
        float4 b = ((const float4*)gtb)[j];
        float area_b = (b.z - b.x) * (b.w - b.y);
        float cx = (b.x + b.z) * 0.5f, cy = (b.y + b.w) * 0.5f;
        int lab = glab[j];
        for (int t = tid; t < NPAD; t += 256) {
            float4 A = g_pk0[t];
            float4 P = g_pk1[t];
            float iou = iou_fast(A, P.w, b, area_b);
            float cost = 1e8f;
            if (P.w > 0.0f) {
                float dx = P.x - cx, dy = P.y - cy;
                float d2 = __fmaf_rn(dx, dx, dy * dy);
                float l = __ldg(ps + (size_t)t * N_C + lab);
                cost = cost_tail(iou, d2, P.z, l);
            }
            ins13_iou(li, iou);
            ins13_key(lk, (((u64)__float_as_uint(cost)) << 32) | (u32)t);
        }
    }

    float myv; u64 myk;
    warp_extract13<KK>(li, lk, myv, myk);

    __shared__ float s_v[8 * KK];
    __shared__ u64   s_k[8 * KK];
    if (lane < KK) {
        s_v[w * KK + lane] = myv;
        s_k[w * KK + lane] = myk;
    }
    __syncthreads();

    if (w == 0) {
        float fi[KK]; u64 fk[KK];
        #pragma unroll
        for (int k = 0; k < KK; k++) { fi[k] = 0.0f; fk[k] = UMAX; }
        #pragma unroll
        for (int r = 0; r < 4; r++) {
            int t = lane + r * 32;
            if (t < 8 * KK) {
                ins13_iou(fi, s_v[t]);
                ins13_key(fk, s_k[t]);
            }
        }
        float gv; u64 gk;
        warp_extract13<KK>(fi, fk, gv, gk);

        // descending-order sequential sum of top-13 ious
        float sum = 0.0f;
        #pragma unroll
        for (int r = 0; r < KK; r++)
            sum += __shfl_sync(0xFFFFFFFFu, gv, r);
        int ks = (int)sum;
        if (ks < 1)  ks = 1;
        if (ks > KK) ks = KK;

        if (lane < ks) {
            int i = (int)(gk & 0xFFFFFFFFull);
            if (i < N_P) {
                atomicAdd(&g_cnt[i], 1);
                g_mgt[i] = j;              // racy only when cnt>1
            }
        }
    }
}

// ---------------- kernel R: resolve + reset for next replay ------------------
__global__ void __launch_bounds__(256) resolve_kernel(const float* __restrict__ gtb,
                                                      const int*   __restrict__ glab,
                                                      float* __restrict__ out) {
    __shared__ float4 sgt[N_G];
    __shared__ int    sgl[N_G];
    int tid = threadIdx.x;
    sgt[tid] = ((const float4*)gtb)[tid];
    sgl[tid] = glab[tid];
    __syncthreads();
    int i = blockIdx.x * 256 + tid;      // covers NPAD exactly

    u64 inv = g_amin[i];
    g_amin[i] = 0;                       // reset for next graph replay
    if (blockIdx.x == 0) { g_icnt[tid] = 0; g_ccnt[tid] = 0; }

    if (i < N_P) {
        int c = g_cnt[i];
        g_cnt[i] = 0;                    // reset for next graph replay
        float4 P = g_pk1[i];
        float4 A = g_pk0[i];
        bool valid = P.w > 0.0f;
        int gsel = 0;
        bool fg = false;
        if (c == 1) {
            gsel = g_mgt[i];
            fg = true;
        } else if (c > 1) {
            gsel = (int)((~inv) & 0xFFFFFFFFull);   // exact gated argmin, lowest-j ties
            fg = true;
        }
        float iou = 0.0f;
        if (fg) {
            float4 b = sgt[gsel];
            float area_b = (b.z - b.x) * (b.w - b.y);
            iou = iou_exact(A, P.w, b, area_b);
        }
        bool fin = fg && valid;
        out[i]           = fin ? (float)(gsel + 1)  : 0.0f;
        out[N_P + i]     = fin ? iou                : -1e8f;
        out[2*N_P + i]   = fin ? (float)sgl[gsel]   : -1.0f;
    }
}

// ---------------- launch ------------------------------------------------------
extern "C" void kernel_launch(void* const* d_in, const int* in_sizes, int n_in,
                              void* d_out, int out_size) {
    const float* pred_scores = (const float*)d_in[0];
    const float* priors      = (const float*)d_in[1];
    const float* pred_bboxes = (const float*)d_in[2];
    const float* gt_bboxes   = (const float*)d_in[3];
    const int*   gt_labels   = (const int*)  d_in[4];

    dim3 gS(NCHUNK, GSPLIT);
    pair_scan_kernel<<<gS, 256>>>(pred_scores, priors, pred_bboxes,
                                  gt_bboxes, gt_labels);
    select_kernel<<<N_G, 256>>>(pred_scores, gt_bboxes, gt_labels);
    resolve_kernel<<<NCHUNK, 256>>>(gt_bboxes, gt_labels, (float*)d_out);
}

// round 17
// speedup vs baseline: 1.6438x; 1.6438x over previous
#include <cuda_runtime.h>
#include <math.h>
#include <stdint.h>

#define N_P   33600
#define NPAD  33792                 // 132 * 256
#define N_G   256
#define N_C   80
#define KK    13
#define NCHUNK 132
#define CAPC  2048                  // cost-pool capacity per GT
#define CAPI  4096                  // iou-pool capacity per GT
#define COST_T 96.0f                // screening threshold: cost >= scp - 3e-7
#define DGATE 4.9872f               // scp < 97  <=>  dist < 4.9872
#define UMAX  0xFFFFFFFFFFFFFFFFull

typedef unsigned long long u64;
typedef unsigned int u32;

// ---------------- scratch (device globals; no runtime allocation) ----------
__device__ float4 g_pk0[NPAD];                // pred bbox x1,y1,x2,y2
__device__ float4 g_pk1[NPAD];                // px, py, 1/stride, +-area
__device__ int    g_cnt [N_P];
__device__ int    g_mgt [N_P];
__device__ u64    g_amin[NPAD];               // {costbits, j} gated argmin
__device__ int    g_icnt[N_G];
__device__ int    g_ccnt[N_G];
__device__ float  g_ipool[N_G * CAPI];        // iou>0 values
__device__ u64    g_cpool[N_G * CAPC];        // {costbits, prior idx} for cost<T

// ---------------- fast approx intrinsics ------------------------------------
__device__ __forceinline__ float ex2a(float x){ float r; asm("ex2.approx.f32 %0,%1;" : "=f"(r) : "f"(x)); return r; }
__device__ __forceinline__ float lg2a(float x){ float r; asm("lg2.approx.f32 %0,%1;" : "=f"(r) : "f"(x)); return r; }
__device__ __forceinline__ float sqrta(float x){ float r; asm("sqrt.approx.f32 %0,%1;" : "=f"(r) : "f"(x)); return r; }
__device__ __forceinline__ float rcpa(float x){ float r; asm("rcp.approx.f32 %0,%1;" : "=f"(r) : "f"(x)); return r; }

// ---------------- math helpers (identical everywhere) -----------------------
__device__ __forceinline__ float iou_fast(float4 A, float Pw, float4 b, float area_b) {
    float area_a = fabsf(Pw);
    float ltx = fmaxf(A.x, b.x), lty = fmaxf(A.y, b.y);
    float rbx = fminf(A.z, b.z), rby = fminf(A.w, b.w);
    float w = fmaxf(rbx - ltx, 0.0f), h = fmaxf(rby - lty, 0.0f);
    float inter = w * h;
    float uni = (area_a + area_b) - inter;
    return inter * rcpa(fmaxf(uni, 1e-6f));
}

__device__ __forceinline__ float iou_exact(float4 A, float Pw, float4 b, float area_b) {
    float area_a = fabsf(Pw);
    float ltx = fmaxf(A.x, b.x), lty = fmaxf(A.y, b.y);
    float rbx = fminf(A.z, b.z), rby = fminf(A.w, b.w);
    float w = fmaxf(rbx - ltx, 0.0f), h = fmaxf(rby - lty, 0.0f);
    float inter = w * h;
    float uni = (area_a + area_b) - inter;
    return __fdiv_rn(inter, fmaxf(uni, 1e-6f));
}

__device__ __forceinline__ float cost_tail(float iou, float d2, float inv_st, float l) {
    float dist = sqrta(d2) * inv_st;
    float scp = ex2a(__fmaf_rn(dist, 3.321928094887362f, -9.965784284662087f));
    float e   = ex2a(fabsf(l) * -1.4426950408889634f);
    float inv = rcpa(1.0f + e);
    float s   = (l >= 0.0f) ? inv : e * inv;
    float mm  = __fmaf_rn(lg2a(1.0f + e), 0.6931471805599453f, fmaxf(l, 0.0f));
    float d = iou - s;
    float scale = d * d;
    float bce = __fmaf_rn(-l, iou, mm);
    float ic = lg2a(iou + 1e-7f) * -2.0794415416798357f;
    return __fmaf_rn(bce, scale, ic + scp);
}

// ---------------- lane-local sorted-13 inserts -------------------------------
__device__ __forceinline__ void ins13_iou(float* a, float v) {
    if (v > a[KK-1]) {
        a[KK-1] = v;
        #pragma unroll
        for (int k = KK-1; k > 0; k--)
            if (a[k] > a[k-1]) { float t = a[k-1]; a[k-1] = a[k]; a[k] = t; }
    }
}
__device__ __forceinline__ void ins13_key(u64* a, u64 v) {
    if (v < a[KK-1]) {
        a[KK-1] = v;
        #pragma unroll
        for (int k = KK-1; k > 0; k--)
            if (a[k] < a[k-1]) { u64 t = a[k-1]; a[k-1] = a[k]; a[k] = t; }
    }
}

// interleaved 13-round warp extraction from per-lane sorted lists (length L).
template<int L>
__device__ __forceinline__ void warp_extract13(float* li, u64* lk,
                                               float& myv, u64& myk) {
    int lane = threadIdx.x & 31;
    myv = 0.0f; myk = UMAX;
    #pragma unroll
    for (int r = 0; r < KK; r++) {
        u32 hb = __float_as_uint(li[0]);
        u32 hc = (u32)(lk[0] >> 32);
        u32 hi = (u32)lk[0];
        u32 mb = __reduce_max_sync(0xFFFFFFFFu, hb);
        u32 mc = __reduce_min_sync(0xFFFFFFFFu, hc);
        u32 cand = (hc == mc) ? hi : 0xFFFFFFFFu;
        u32 mi = __reduce_min_sync(0xFFFFFFFFu, cand);
        if (lane == r) {
            myv = __uint_as_float(mb);
            myk = (((u64)mc) << 32) | mi;
        }
        u32 ballv = __ballot_sync(0xFFFFFFFFu, hb == mb);
        if (lane == (__ffs(ballv) - 1)) {
            #pragma unroll
            for (int k = 0; k < L-1; k++) li[k] = li[k+1];
            li[L-1] = 0.0f;
        }
        u32 ballk = __ballot_sync(0xFFFFFFFFu, (hc == mc) && (hi == mi));
        if (lane == (__ffs(ballk) - 1)) {
            #pragma unroll
            for (int k = 0; k < L-1; k++) lk[k] = lk[k+1];
            lk[L-1] = UMAX;
        }
    }
}

// ---------------- kernel P: pack priors + valid mask + init ------------------
__global__ void __launch_bounds__(256) prep_kernel(const float* __restrict__ priors,
                                                   const float* __restrict__ pb,
                                                   const float* __restrict__ gtb) {
    __shared__ float4 svb[N_G];
    int tid = threadIdx.x;
    {
        float4 B = ((const float4*)gtb)[tid];
        bool pad = ((B.x + B.y) + (B.z + B.w)) > 0.0f;
        svb[tid] = pad ? B : make_float4(1e30f, 1e30f, -1e30f, -1e30f);
    }
    if (blockIdx.x == 0) { g_icnt[tid] = 0; g_ccnt[tid] = 0; }
    __syncthreads();
    int i = blockIdx.x * 256 + tid;
    if (i < N_P) {
        float4 PR = ((const float4*)priors)[i];
        float4 A  = ((const float4*)pb)[i];
        float px = PR.x, py = PR.y;
        bool any = false;
        for (int j = 0; j < N_G; j++) {
            float4 B = svb[j];
            if ((px > B.x) && (py > B.y) && (px < B.z) && (py < B.w)) { any = true; break; }
        }
        float area = (A.z - A.x) * (A.w - A.y);
        g_pk0[i] = A;
        g_pk1[i] = make_float4(px, py, rcpa(PR.z), any ? area : -area);
        g_cnt[i] = 0;
    } else {
        g_pk0[i] = make_float4(0.0f, 0.0f, 0.0f, 0.0f);   // degenerate -> iou 0
        g_pk1[i] = make_float4(0.0f, 0.0f, 1.0f, -1.0f);  // invalid
    }
    g_amin[i] = UMAX;
}

// ---------------- kernel S: d2-gated pairwise scan (per-lane atomics) --------
__global__ void __launch_bounds__(256) pair_scan_kernel(const float* __restrict__ ps,
                                                        const float* __restrict__ gtb,
                                                        const int*   __restrict__ glab) {
    __shared__ float4 sb[32];
    __shared__ float4 sm[32];       // area, cx, cy, unused
    __shared__ int    slab[32];
    int tid = threadIdx.x;
    int chunk = blockIdx.x;                // 0..131
    int g0 = blockIdx.y * 32;
    if (tid < 32) {
        int j = g0 + tid;
        float4 B = ((const float4*)gtb)[j];
        sb[tid] = B;
        sm[tid] = make_float4((B.z - B.x) * (B.w - B.y),
                              (B.x + B.z) * 0.5f, (B.y + B.w) * 0.5f, 0.0f);
        slab[tid] = glab[j];
    }
    __syncthreads();

    int i = chunk * 256 + tid;
    float4 A = g_pk0[i];
    float4 P = g_pk1[i];
    bool valid = P.w > 0.0f;
    const float* psrow = ps + (size_t)i * N_C;
    float stv = __fdiv_rn(DGATE, P.z);
    float d2max = valid ? stv * stv : -1.0f;

    u64 bestk = UMAX;
    #pragma unroll 4
    for (int jj = 0; jj < 32; jj++) {
        int j = g0 + jj;
        float4 b  = sb[jj];
        float4 m4 = sm[jj];
        float iou = iou_fast(A, P.w, b, m4.x);

        // iou pool (iou > 0): per-lane slot via atomic return
        if (iou > 0.0f) {
            int slot = atomicAdd(&g_icnt[j], 1);
            if (slot < CAPI) g_ipool[j * CAPI + slot] = iou;
        }

        // cost: d2 gate, then full tail for the rare near pairs
        float dx = P.x - m4.y, dy = P.y - m4.z;
        float d2 = __fmaf_rn(dx, dx, dy * dy);
        if (d2 < d2max) {
            float l = __ldg(psrow + slab[jj]);
            float cost = cost_tail(iou, d2, P.z, l);
            u64 key = (((u64)__float_as_uint(cost)) << 32) | (u32)j;
            if (key < bestk) bestk = key;
            if (cost < COST_T) {
                int slot = atomicAdd(&g_ccnt[j], 1);
                if (slot < CAPC)
                    g_cpool[j * CAPC + slot] =
                        (((u64)__float_as_uint(cost)) << 32) | (u32)i;
            }
        }
    }
    // exact for multi-matched priors: their true min cost < 96 < gated-out costs
    if (bestk != UMAX) atomicMin(&g_amin[i], bestk);
}

// ---------------- kernel M: per-GT exact top-13 from pools + scatter ---------
__global__ void __launch_bounds__(256) select_kernel(const float* __restrict__ ps,
                                                     const float* __restrict__ gtb,
                                                     const int*   __restrict__ glab) {
    int j = blockIdx.x;
    int tid = threadIdx.x;
    int w = tid >> 5, lane = tid & 31;

    int cntI = g_icnt[j];
    int cntC = g_ccnt[j];
    bool fb = (cntC < KK) || (cntC > CAPC) || (cntI > CAPI);

    float li[KK]; u64 lk[KK];
    #pragma unroll
    for (int k = 0; k < KK; k++) { li[k] = 0.0f; lk[k] = UMAX; }

    if (!fb) {
        const float* ip = g_ipool + j * CAPI;
        const u64*   cp = g_cpool + j * CAPC;
        for (int t = tid; t < cntI; t += 256) ins13_iou(li, ip[t]);
        for (int t = tid; t < cntC; t += 256) ins13_key(lk, cp[t]);
    } else {
        // exact full-column rescan (correctness guarantee; ~never runs)
        float4 b = ((const float4*)gtb)[j];
        float area_b = (b.z - b.x) * (b.w - b.y);
        float cx = (b.x + b.z) * 0.5f, cy = (b.y + b.w) * 0.5f;
        int lab = glab[j];
        for (int t = tid; t < NPAD; t += 256) {
            float4 A = g_pk0[t];
            float4 P = g_pk1[t];
            float iou = iou_fast(A, P.w, b, area_b);
            float cost = 1e8f;
            if (P.w > 0.0f) {
                float dx = P.x - cx, dy = P.y - cy;
                float d2 = __fmaf_rn(dx, dx, dy * dy);
                float l = __ldg(ps + (size_t)t * N_C + lab);
                cost = cost_tail(iou, d2, P.z, l);
            }
            ins13_iou(li, iou);
            ins13_key(lk, (((u64)__float_as_uint(cost)) << 32) | (u32)t);
        }
    }

    float myv; u64 myk;
    warp_extract13<KK>(li, lk, myv, myk);

    __shared__ float s_v[8 * KK];
    __shared__ u64   s_k[8 * KK];
    if (lane < KK) {
        s_v[w * KK + lane] = myv;
        s_k[w * KK + lane] = myk;
    }
    __syncthreads();

    if (w == 0) {
        float fi[KK]; u64 fk[KK];
        #pragma unroll
        for (int k = 0; k < KK; k++) { fi[k] = 0.0f; fk[k] = UMAX; }
        #pragma unroll
        for (int r = 0; r < 4; r++) {
            int t = lane + r * 32;
            if (t < 8 * KK) {
                ins13_iou(fi, s_v[t]);
                ins13_key(fk, s_k[t]);
            }
        }
        float gv; u64 gk;
        warp_extract13<KK>(fi, fk, gv, gk);

        // descending-order sequential sum of top-13 ious
        float sum = 0.0f;
        #pragma unroll
        for (int r = 0; r < KK; r++)
            sum += __shfl_sync(0xFFFFFFFFu, gv, r);
        int ks = (int)sum;
        if (ks < 1)  ks = 1;
        if (ks > KK) ks = KK;

        if (lane < ks) {
            int i = (int)(gk & 0xFFFFFFFFull);
            if (i < N_P) {
                atomicAdd(&g_cnt[i], 1);
                g_mgt[i] = j;              // racy only when cnt>1
            }
        }
    }
}

// ---------------- kernel R: resolve (loop-free, direct loads) ----------------
__global__ void __launch_bounds__(256) resolve_kernel(const float* __restrict__ gtb,
                                                      const int*   __restrict__ glab,
                                                      float* __restrict__ out) {
    int i = blockIdx.x * 256 + threadIdx.x;
    if (i >= N_P) return;
    float4 P = g_pk1[i];
    float4 A = g_pk0[i];
    bool valid = P.w > 0.0f;
    int c = g_cnt[i];
    int gsel = 0;
    bool fg = false;
    if (c == 1) {
        gsel = g_mgt[i];
        fg = true;
    } else if (c > 1) {
        gsel = (int)(g_amin[i] & 0xFFFFFFFFull);   // exact gated argmin, lowest-j ties
        fg = true;
    }
    float iou = 0.0f;
    float lab = -1.0f;
    if (fg) {
        float4 b = __ldg(&((const float4*)gtb)[gsel]);
        float area_b = (b.z - b.x) * (b.w - b.y);
        iou = iou_exact(A, P.w, b, area_b);
        lab = (float)__ldg(&glab[gsel]);
    }
    bool fin = fg && valid;
    out[i]           = fin ? (float)(gsel + 1)  : 0.0f;
    out[N_P + i]     = fin ? iou                : -1e8f;
    out[2*N_P + i]   = fin ? lab                : -1.0f;
}

// ---------------- launch ------------------------------------------------------
extern "C" void kernel_launch(void* const* d_in, const int* in_sizes, int n_in,
                              void* d_out, int out_size) {
    const float* pred_scores = (const float*)d_in[0];
    const float* priors      = (const float*)d_in[1];
    const float* pred_bboxes = (const float*)d_in[2];
    const float* gt_bboxes   = (const float*)d_in[3];
    const int*   gt_labels   = (const int*)  d_in[4];

    prep_kernel<<<NCHUNK, 256>>>(priors, pred_bboxes, gt_bboxes);
    dim3 gS(NCHUNK, 8);
    pair_scan_kernel<<<gS, 256>>>(pred_scores, gt_bboxes, gt_labels);
    select_kernel<<<N_G, 256>>>(pred_scores, gt_bboxes, gt_labels);
    resolve_kernel<<<NCHUNK, 256>>>(gt_bboxes, gt_labels, (float*)d_out);
}